// round 1
// baseline (speedup 1.0000x reference)
#include <cuda_runtime.h>

#define BB 16
#define TT 2048
#define CC 512
#define HH 64
#define SCALE 0.125f
#define SQ 68
#define SE 68

// Scratch for Q, K, V projections (B*T*H floats each = 8MB each)
__device__ float g_q[BB * TT * HH];
__device__ float g_k[BB * TT * HH];
__device__ float g_v[BB * TT * HH];

// ---------------------------------------------------------------------------
// Kernel 1: QKV projection. X (B*T, C) @ W (C, H) -> (B*T, H), one W per
// blockIdx.y. 64x64 output tile per block, 256 threads, 4x4 per thread.
// ---------------------------------------------------------------------------
__global__ __launch_bounds__(256) void qkv_kernel(
    const float* __restrict__ x, const float* __restrict__ Wq,
    const float* __restrict__ Wk, const float* __restrict__ Wv) {
  const float* W = blockIdx.y == 0 ? Wq : (blockIdx.y == 1 ? Wk : Wv);
  float* outp = blockIdx.y == 0 ? g_q : (blockIdx.y == 1 ? g_k : g_v);
  int row0 = blockIdx.x * 64;
  __shared__ float Xs[32][SQ];  // [k][m]
  __shared__ float Ws[32][SQ];  // [k][n]
  int tid = threadIdx.x;
  int tx = tid & 15, ty = tid >> 4;
  float acc[4][4] = {};
  for (int k0 = 0; k0 < CC; k0 += 32) {
    for (int i = tid; i < 2048; i += 256) {
      int m = i >> 5, kk = i & 31;
      Xs[kk][m] = x[(size_t)(row0 + m) * CC + k0 + kk];
    }
    for (int i = tid; i < 2048; i += 256) {
      int kk = i >> 6, n = i & 63;
      Ws[kk][n] = W[(size_t)(k0 + kk) * HH + n];
    }
    __syncthreads();
#pragma unroll
    for (int kk = 0; kk < 32; kk++) {
      float4 a = *(const float4*)&Xs[kk][4 * ty];
      float4 b4 = *(const float4*)&Ws[kk][4 * tx];
      float av[4] = {a.x, a.y, a.z, a.w};
      float bv[4] = {b4.x, b4.y, b4.z, b4.w};
#pragma unroll
      for (int ii = 0; ii < 4; ii++)
#pragma unroll
        for (int jj = 0; jj < 4; jj++) acc[ii][jj] += av[ii] * bv[jj];
    }
    __syncthreads();
  }
#pragma unroll
  for (int ii = 0; ii < 4; ii++) {
    float4 o = make_float4(acc[ii][0], acc[ii][1], acc[ii][2], acc[ii][3]);
    *(float4*)&outp[(size_t)(row0 + 4 * ty + ii) * HH + 4 * tx] = o;
  }
}

// ---------------------------------------------------------------------------
// Kernel 2: fused causal attention with the reference's (transposed) skew:
//   att[t,s] = scale*q_t.k_s + ( s==t   : q_t.Er[T-1]
//                                s==t-1 : 0
//                                s<=t-2 : q_{s+1}.Er[t-s-2] )
// Flash-style: 64 query rows per block, loop 64-wide key tiles. 256 threads,
// 4x4 per thread. rel term computed as second dot against a shifted Q tile
// (Qrs[j] = q[s0+1+j]) and an Er band (Ers[x] = Er[t0-s0-65+x]).
// ---------------------------------------------------------------------------
__global__ __launch_bounds__(256) void attn_kernel(const float* __restrict__ Er,
                                                   float* __restrict__ out) {
  int b = blockIdx.y;
  int t0 = blockIdx.x * 64;
  const float* Q = g_q + (size_t)b * TT * HH;
  const float* K = g_k + (size_t)b * TT * HH;
  const float* V = g_v + (size_t)b * TT * HH;
  extern __shared__ float sm[];
  float* Qs = sm;               // [64][SQ]  [row][h]
  float* Ks = Qs + 64 * SQ;     // [64][SQ]
  float* Vs = Ks + 64 * SQ;     // [64][SQ]
  float* Qrs = Vs + 64 * SQ;    // [64][SQ]  shifted q rows
  float* Ps = Qrs + 64 * SQ;    // [64][SQ]  exp(S) tile
  float* Ers = Ps + 64 * SQ;    // [128][SE] Er band
  float* ds = Ers + 128 * SE;   // [64] diagonal rel term

  int tid = threadIdx.x;
  int tx = tid & 15, ty = tid >> 4;

  for (int idx = tid; idx < 64 * 16; idx += 256) {
    int r = idx >> 4, h4 = (idx & 15) << 2;
    *(float4*)&Qs[r * SQ + h4] = *(const float4*)&Q[(size_t)(t0 + r) * HH + h4];
  }
  __syncthreads();
  if (tid < 64) {
    float acc = 0.f;
    const float* el = Er + (size_t)(TT - 1) * HH;
#pragma unroll
    for (int h = 0; h < HH; h++) acc += Qs[tid * SQ + h] * el[h];
    ds[tid] = acc;
  }

  float O[4][4] = {};
  float mrow[4] = {-1e30f, -1e30f, -1e30f, -1e30f};
  float lrow[4] = {};

  for (int s0 = 0; s0 <= t0; s0 += 64) {
    __syncthreads();  // smem reuse guard (and ds on first iter)
    int rbase = t0 - s0 - 65;
    for (int idx = tid; idx < 64 * 16; idx += 256) {
      int r = idx >> 4, h4 = (idx & 15) << 2;
      *(float4*)&Ks[r * SQ + h4] =
          *(const float4*)&K[(size_t)(s0 + r) * HH + h4];
      *(float4*)&Vs[r * SQ + h4] =
          *(const float4*)&V[(size_t)(s0 + r) * HH + h4];
      int rq = s0 + 1 + r;
      if (rq > TT - 1) rq = TT - 1;  // clamped rows only feed masked slots
      *(float4*)&Qrs[r * SQ + h4] = *(const float4*)&Q[(size_t)rq * HH + h4];
    }
    for (int idx = tid; idx < 128 * 16; idx += 256) {
      int xr = idx >> 4, h4 = (idx & 15) << 2;
      int r = rbase + xr;
      r = r < 0 ? 0 : (r > TT - 1 ? TT - 1 : r);  // invalid rows unused
      *(float4*)&Ers[xr * SE + h4] = *(const float4*)&Er[(size_t)r * HH + h4];
    }
    __syncthreads();

    float sqk[4][4] = {};
    float srl[4][4] = {};
    int xb = 4 * ty - 4 * tx + 63;  // Ers row for (ii-jj)=0
#pragma unroll 2
    for (int h0 = 0; h0 < HH; h0 += 4) {
      float4 qf[4], kf[4], qr[4], ef[7];
#pragma unroll
      for (int u = 0; u < 4; u++) {
        qf[u] = *(const float4*)&Qs[(4 * ty + u) * SQ + h0];
        kf[u] = *(const float4*)&Ks[(4 * tx + u) * SQ + h0];
        qr[u] = *(const float4*)&Qrs[(4 * tx + u) * SQ + h0];
      }
#pragma unroll
      for (int w = 0; w < 7; w++)
        ef[w] = *(const float4*)&Ers[(xb - 3 + w) * SE + h0];
#pragma unroll
      for (int ii = 0; ii < 4; ii++)
#pragma unroll
        for (int jj = 0; jj < 4; jj++) {
          sqk[ii][jj] += qf[ii].x * kf[jj].x + qf[ii].y * kf[jj].y +
                         qf[ii].z * kf[jj].z + qf[ii].w * kf[jj].w;
          float4 e = ef[ii - jj + 3];
          srl[ii][jj] += e.x * qr[jj].x + e.y * qr[jj].y + e.z * qr[jj].z +
                         e.w * qr[jj].w;
        }
    }

#pragma unroll
    for (int ii = 0; ii < 4; ii++) {
      int t = t0 + 4 * ty + ii;
      float sv[4];
      float rowm = -1e30f;
#pragma unroll
      for (int jj = 0; jj < 4; jj++) {
        int s = s0 + 4 * tx + jj;
        float v = SCALE * sqk[ii][jj];
        if (s <= t - 2)
          v += srl[ii][jj];
        else if (s == t)
          v += ds[4 * ty + ii];
        if (s > t) v = -1e30f;
        sv[jj] = v;
        rowm = fmaxf(rowm, v);
      }
#pragma unroll
      for (int off = 8; off; off >>= 1)
        rowm = fmaxf(rowm, __shfl_xor_sync(0xffffffffu, rowm, off));
      float mnew = fmaxf(mrow[ii], rowm);
      float alpha = __expf(mrow[ii] - mnew);
      float rs = 0.f;
#pragma unroll
      for (int jj = 0; jj < 4; jj++) {
        float p = __expf(sv[jj] - mnew);
        Ps[(4 * ty + ii) * SQ + 4 * tx + jj] = p;
        rs += p;
      }
#pragma unroll
      for (int off = 8; off; off >>= 1)
        rs += __shfl_xor_sync(0xffffffffu, rs, off);
      lrow[ii] = alpha * lrow[ii] + rs;
      mrow[ii] = mnew;
#pragma unroll
      for (int cc = 0; cc < 4; cc++) O[ii][cc] *= alpha;
    }
    __syncthreads();
#pragma unroll 4
    for (int jj = 0; jj < 64; jj++) {
      float4 vf = *(const float4*)&Vs[jj * SQ + 4 * tx];
#pragma unroll
      for (int ii = 0; ii < 4; ii++) {
        float p = Ps[(4 * ty + ii) * SQ + jj];
        O[ii][0] += p * vf.x;
        O[ii][1] += p * vf.y;
        O[ii][2] += p * vf.z;
        O[ii][3] += p * vf.w;
      }
    }
  }

#pragma unroll
  for (int ii = 0; ii < 4; ii++) {
    float inv = 1.f / lrow[ii];
    int t = t0 + 4 * ty + ii;
    float4 o = make_float4(O[ii][0] * inv, O[ii][1] * inv, O[ii][2] * inv,
                           O[ii][3] * inv);
    *(float4*)&out[((size_t)b * TT + t) * HH + 4 * tx] = o;
  }
}

#define ATTN_SMEM ((5 * 64 * SQ + 128 * SE + 64) * 4)

extern "C" void kernel_launch(void* const* d_in, const int* in_sizes, int n_in,
                              void* d_out, int out_size) {
  (void)in_sizes;
  (void)n_in;
  (void)out_size;
  const float* x = (const float*)d_in[0];
  const float* Wq = (const float*)d_in[1];
  const float* Wk = (const float*)d_in[2];
  const float* Wv = (const float*)d_in[3];
  const float* Er = (const float*)d_in[4];
  float* out = (float*)d_out;

  cudaFuncSetAttribute(attn_kernel, cudaFuncAttributeMaxDynamicSharedMemorySize,
                       ATTN_SMEM);

  qkv_kernel<<<dim3((BB * TT) / 64, 3), 256>>>(x, Wq, Wk, Wv);
  attn_kernel<<<dim3(TT / 64, BB), 256, ATTN_SMEM>>>(Er, out);
}

// round 3
// speedup vs baseline: 1.9346x; 1.9346x over previous
#include <cuda_runtime.h>
#include <cstdint>

#define BB 16
#define TT 2048
#define CC 512
#define HH 64
#define SCALE 0.125f

__device__ float g_q[BB * TT * HH];
__device__ float g_k[BB * TT * HH];
__device__ float g_v[BB * TT * HH];

__device__ __forceinline__ uint32_t f2tf(float f) {
  uint32_t u;
  asm("cvt.rna.tf32.f32 %0, %1;" : "=r"(u) : "f"(f));
  return u;
}

// hi/lo tf32 split: x ~= hi + lo with ~fp32 total precision
__device__ __forceinline__ void split(float x, uint32_t& h, uint32_t& l) {
  h = f2tf(x);
  l = f2tf(x - __uint_as_float(h));
}

// m16n8k8 tf32 MMA. A row-major, B col-major, C/D f32.
__device__ __forceinline__ void mma8(float* c, uint32_t a0, uint32_t a1,
                                     uint32_t a2, uint32_t a3, uint32_t b0,
                                     uint32_t b1) {
  asm volatile(
      "mma.sync.aligned.m16n8k8.row.col.f32.tf32.tf32.f32 "
      "{%0,%1,%2,%3}, {%4,%5,%6,%7}, {%8,%9}, {%0,%1,%2,%3};"
      : "+f"(c[0]), "+f"(c[1]), "+f"(c[2]), "+f"(c[3])
      : "r"(a0), "r"(a1), "r"(a2), "r"(a3), "r"(b0), "r"(b1));
}

// 3xTF32: hi*hi + hi*lo + lo*hi
__device__ __forceinline__ void mma3(float* c, const uint32_t* ah,
                                     const uint32_t* al, uint32_t bh0,
                                     uint32_t bh1, uint32_t bl0, uint32_t bl1) {
  mma8(c, ah[0], ah[1], ah[2], ah[3], bl0, bl1);
  mma8(c, al[0], al[1], al[2], al[3], bh0, bh1);
  mma8(c, ah[0], ah[1], ah[2], ah[3], bh0, bh1);
}

// bank-conflict swizzle: flip col bit2 on alternating 4-row groups
#define SW(row, col) ((col) ^ ((((row) >> 2) & 1) << 2))

// ---------------------------------------------------------------------------
// QKV projection: X(32768,512) @ [Wq|Wk|Wv](512,192), 3xTF32 MMA.
// ---------------------------------------------------------------------------
#define PX 40
#define PW 200
__global__ __launch_bounds__(256) void qkv_mma(const float* __restrict__ x,
                                               const float* __restrict__ Wq,
                                               const float* __restrict__ Wk,
                                               const float* __restrict__ Wv) {
  __shared__ float Xs[64 * PX];
  __shared__ float Ws[32 * PW];
  int tid = threadIdx.x, w = tid >> 5, lane = tid & 31;
  int g = lane >> 2, tg = lane & 3;
  int row0 = blockIdx.x * 64;
  int mt = w & 3, nh = w >> 2;
  float acc[12][4] = {};

  for (int k0 = 0; k0 < CC; k0 += 32) {
    __syncthreads();
    for (int i = tid; i < 512; i += 256) {  // X 64x32
      int r = i >> 3, h4 = (i & 7) << 2;
      float4 v4 = *(const float4*)&x[(size_t)(row0 + r) * CC + k0 + h4];
      *(float4*)&Xs[r * PX + SW(r, h4)] = v4;
    }
    for (int i = tid; i < 1536; i += 256) {  // W 32x192
      int k = i / 48, n4 = (i % 48) * 4;
      int m = n4 >> 6, nn = n4 & 63;
      const float* Wm = m == 0 ? Wq : (m == 1 ? Wk : Wv);
      *(float4*)&Ws[k * PW + n4] =
          *(const float4*)&Wm[(size_t)(k0 + k) * HH + nn];
    }
    __syncthreads();
#pragma unroll
    for (int k8 = 0; k8 < 32; k8 += 8) {
      int r1 = 16 * mt + g, r2 = r1 + 8;
      uint32_t ah[4], al[4];
      split(Xs[r1 * PX + SW(r1, k8 + tg)], ah[0], al[0]);
      split(Xs[r2 * PX + SW(r2, k8 + tg)], ah[1], al[1]);
      split(Xs[r1 * PX + SW(r1, k8 + tg + 4)], ah[2], al[2]);
      split(Xs[r2 * PX + SW(r2, k8 + tg + 4)], ah[3], al[3]);
#pragma unroll
      for (int v = 0; v < 12; v++) {
        int n0 = 8 * (12 * nh + v);
        uint32_t bh0, bl0, bh1, bl1;
        split(Ws[(k8 + tg) * PW + n0 + g], bh0, bl0);
        split(Ws[(k8 + tg + 4) * PW + n0 + g], bh1, bl1);
        mma3(acc[v], ah, al, bh0, bh1, bl0, bl1);
      }
    }
  }
#pragma unroll
  for (int v = 0; v < 12; v++) {
    int ncol = 8 * (12 * nh + v) + 2 * tg;
    int m = ncol >> 6, nn = ncol & 63;
    float* o = m == 0 ? g_q : (m == 1 ? g_k : g_v);
    int r0 = row0 + 16 * mt + g;
    *(float2*)&o[(size_t)r0 * HH + nn] = make_float2(acc[v][0], acc[v][1]);
    *(float2*)&o[(size_t)(r0 + 8) * HH + nn] =
        make_float2(acc[v][2], acc[v][3]);
  }
}

// ---------------------------------------------------------------------------
// Fused attention, 3xTF32 MMA. 64 query rows/CTA, key tiles of 32.
//   att[t,s] = scale*q_t.k_s + ( s==t: q_t.Er[T-1] ; s==t-1: 0 ;
//                                s<=t-2: q_{s+1}.Er[t-s-2] )
// rel via GEMM G[j][x] = q[s0+1+j].Er[rbase+x], rbase=t0-s0-33,
// gathered as srl[i][j] = G[j][i-j+31].
// ---------------------------------------------------------------------------
#define PT 72
#define PS 34
#define PG 100
#define SM_FLOATS \
  (64 * PT + 3 * 32 * PT + 96 * PT + 64 * PS + 32 * PG + 256 + 512)

__global__ __launch_bounds__(256) void attn_mma(const float* __restrict__ Er,
                                                float* __restrict__ out) {
  extern __shared__ float sm[];
  float* Qs = sm;              // 64 x PT (swizzled)
  float* Ks = Qs + 64 * PT;    // 32 x PT
  float* Vs = Ks + 32 * PT;    // 32 x PT
  float* Qrs = Vs + 32 * PT;   // 32 x PT
  float* Ers = Qrs + 32 * PT;  // 96 x PT
  float* Ss = Ers + 96 * PT;   // 64 x PS (S then P)
  float* Gs = Ss + 64 * PS;    // 32 x PG
  float* ds = Gs + 32 * PG;    // 64
  float* ms = ds + 64;         // 64
  float* ls = ms + 64;         // 64
  float* as_ = ls + 64;        // 64
  float* pmax = as_ + 64;      // 4 x 64
  float* psum = pmax + 256;    // 4 x 64

  int tid = threadIdx.x, w = tid >> 5, lane = tid & 31;
  int g = lane >> 2, tg = lane & 3;
  int b = blockIdx.y, t0 = blockIdx.x * 64;
  const float* Q = g_q + (size_t)b * TT * HH;
  const float* K = g_k + (size_t)b * TT * HH;
  const float* V = g_v + (size_t)b * TT * HH;

  int smt = w & 3, snh = w >> 2;            // S & AV partition
  int gmt = w & 1, gnb = w >> 1;            // G partition
  int sr = tid & 63, sc = (tid >> 6) << 3;  // softmax lanes

  for (int i = tid; i < 1024; i += 256) {  // Q tile 64x64
    int r = i >> 4, h4 = (i & 15) << 2;
    *(float4*)&Qs[r * PT + SW(r, h4)] =
        *(const float4*)&Q[(size_t)(t0 + r) * HH + h4];
  }
  __syncthreads();
  if (tid < 64) {
    float acc = 0.f;
    const float* el = Er + (size_t)(TT - 1) * HH;
#pragma unroll
    for (int h = 0; h < HH; h++) acc += Qs[tid * PT + SW(tid, h)] * el[h];
    ds[tid] = acc;
    ms[tid] = -1e30f;
    ls[tid] = 0.f;
  }

  float O[4][4] = {};

  for (int s0 = 0; s0 <= t0 + 32; s0 += 32) {
    __syncthreads();
    int rbase = t0 - s0 - 33;
    for (int i = tid; i < 512; i += 256) {  // K,V,Qr tiles 32x64
      int r = i >> 4, h4 = (i & 15) << 2;
      int c = r * PT + SW(r, h4);
      *(float4*)&Ks[c] = *(const float4*)&K[(size_t)(s0 + r) * HH + h4];
      *(float4*)&Vs[c] = *(const float4*)&V[(size_t)(s0 + r) * HH + h4];
      int rq = s0 + 1 + r;
      if (rq > TT - 1) rq = TT - 1;  // clamped rows feed only masked slots
      *(float4*)&Qrs[c] = *(const float4*)&Q[(size_t)rq * HH + h4];
    }
    for (int i = tid; i < 1536; i += 256) {  // Ers 96x64
      int xr = i >> 4, h4 = (i & 15) << 2;
      int r = rbase + xr;
      if (r < 0) r = 0;  // negative rows unused
      *(float4*)&Ers[xr * PT + SW(xr, h4)] =
          *(const float4*)&Er[(size_t)r * HH + h4];
    }
    __syncthreads();

    // S = Q @ K^T  (64x32)
    {
      float sf[2][4] = {};
      int r1 = 16 * smt + g, r2 = r1 + 8;
#pragma unroll
      for (int k8 = 0; k8 < 64; k8 += 8) {
        uint32_t ah[4], al[4];
        split(Qs[r1 * PT + SW(r1, k8 + tg)], ah[0], al[0]);
        split(Qs[r2 * PT + SW(r2, k8 + tg)], ah[1], al[1]);
        split(Qs[r1 * PT + SW(r1, k8 + tg + 4)], ah[2], al[2]);
        split(Qs[r2 * PT + SW(r2, k8 + tg + 4)], ah[3], al[3]);
#pragma unroll
        for (int u2 = 0; u2 < 2; u2++) {
          int br = 16 * snh + 8 * u2 + g;
          uint32_t bh0, bl0, bh1, bl1;
          split(Ks[br * PT + SW(br, k8 + tg)], bh0, bl0);
          split(Ks[br * PT + SW(br, k8 + tg + 4)], bh1, bl1);
          mma3(sf[u2], ah, al, bh0, bh1, bl0, bl1);
        }
      }
#pragma unroll
      for (int u2 = 0; u2 < 2; u2++) {
        int n0 = 16 * snh + 8 * u2 + 2 * tg;
        *(float2*)&Ss[r1 * PS + n0] = make_float2(sf[u2][0], sf[u2][1]);
        *(float2*)&Ss[r2 * PS + n0] = make_float2(sf[u2][2], sf[u2][3]);
      }
    }
    // G = Qr @ Ers^T  (32x96)
    {
      float gf[3][4] = {};
      int r1 = 16 * gmt + g, r2 = r1 + 8;
#pragma unroll
      for (int k8 = 0; k8 < 64; k8 += 8) {
        uint32_t ah[4], al[4];
        split(Qrs[r1 * PT + SW(r1, k8 + tg)], ah[0], al[0]);
        split(Qrs[r2 * PT + SW(r2, k8 + tg)], ah[1], al[1]);
        split(Qrs[r1 * PT + SW(r1, k8 + tg + 4)], ah[2], al[2]);
        split(Qrs[r2 * PT + SW(r2, k8 + tg + 4)], ah[3], al[3]);
#pragma unroll
        for (int v = 0; v < 3; v++) {
          int br = 8 * (3 * gnb + v) + g;
          uint32_t bh0, bl0, bh1, bl1;
          split(Ers[br * PT + SW(br, k8 + tg)], bh0, bl0);
          split(Ers[br * PT + SW(br, k8 + tg + 4)], bh1, bl1);
          mma3(gf[v], ah, al, bh0, bh1, bl0, bl1);
        }
      }
#pragma unroll
      for (int v = 0; v < 3; v++) {
        int n0 = 8 * (3 * gnb + v) + 2 * tg;
        *(float2*)&Gs[r1 * PG + n0] = make_float2(gf[v][0], gf[v][1]);
        *(float2*)&Gs[r2 * PG + n0] = make_float2(gf[v][2], gf[v][3]);
      }
    }
    __syncthreads();

    // softmax
    float vvals[8];
    {
      int t = t0 + sr;
      float pm = -1e30f;
#pragma unroll
      for (int c = 0; c < 8; c++) {
        int j = sc + c, s = s0 + j;
        float vv = SCALE * Ss[sr * PS + j];
        if (s <= t - 2)
          vv += Gs[j * PG + (sr - j + 31)];
        else if (s == t)
          vv += ds[sr];
        if (s > t) vv = -1e30f;
        vvals[c] = vv;
        pm = fmaxf(pm, vv);
      }
      pmax[(tid >> 6) * 64 + sr] = pm;
    }
    __syncthreads();
    if (tid < 64) {
      float mo = ms[tid];
      float mn = fmaxf(fmaxf(fmaxf(pmax[tid], pmax[64 + tid]),
                             fmaxf(pmax[128 + tid], pmax[192 + tid])),
                       mo);
      ms[tid] = mn;
      as_[tid] = __expf(mo - mn);
    }
    __syncthreads();
    {
      float mn = ms[sr];
      float rs = 0.f;
#pragma unroll
      for (int c = 0; c < 8; c++) {
        float p = __expf(vvals[c] - mn);
        rs += p;
        Ss[sr * PS + sc + c] = p;
      }
      psum[(tid >> 6) * 64 + sr] = rs;
      float a1 = as_[16 * smt + g], a2 = as_[16 * smt + g + 8];
#pragma unroll
      for (int v = 0; v < 4; v++) {
        O[v][0] *= a1;
        O[v][1] *= a1;
        O[v][2] *= a2;
        O[v][3] *= a2;
      }
    }
    __syncthreads();
    if (tid < 64)
      ls[tid] = as_[tid] * ls[tid] + (psum[tid] + psum[64 + tid]) +
                (psum[128 + tid] + psum[192 + tid]);
    // O += P(64x32) @ V(32x64)
    {
      int r1 = 16 * smt + g, r2 = r1 + 8;
#pragma unroll
      for (int k8 = 0; k8 < 32; k8 += 8) {
        uint32_t ah[4], al[4];
        split(Ss[r1 * PS + k8 + tg], ah[0], al[0]);
        split(Ss[r2 * PS + k8 + tg], ah[1], al[1]);
        split(Ss[r1 * PS + k8 + tg + 4], ah[2], al[2]);
        split(Ss[r2 * PS + k8 + tg + 4], ah[3], al[3]);
#pragma unroll
        for (int v = 0; v < 4; v++) {
          int n0 = 32 * snh + 8 * v;
          int br = k8 + tg;
          uint32_t bh0, bl0, bh1, bl1;
          split(Vs[br * PT + SW(br, n0 + g)], bh0, bl0);
          split(Vs[(br + 4) * PT + SW(br + 4, n0 + g)], bh1, bl1);
          mma3(O[v], ah, al, bh0, bh1, bl0, bl1);
        }
      }
    }
  }

  __syncthreads();
  int r1 = 16 * smt + g, r2 = r1 + 8;
  float inv1 = 1.f / ls[r1], inv2 = 1.f / ls[r2];
#pragma unroll
  for (int v = 0; v < 4; v++) {
    int nc = 32 * snh + 8 * v + 2 * tg;
    *(float2*)&out[((size_t)b * TT + t0 + r1) * HH + nc] =
        make_float2(O[v][0] * inv1, O[v][1] * inv1);
    *(float2*)&out[((size_t)b * TT + t0 + r2) * HH + nc] =
        make_float2(O[v][2] * inv2, O[v][3] * inv2);
  }
}

extern "C" void kernel_launch(void* const* d_in, const int* in_sizes, int n_in,
                              void* d_out, int out_size) {
  (void)in_sizes;
  (void)n_in;
  (void)out_size;
  const float* x = (const float*)d_in[0];
  const float* Wq = (const float*)d_in[1];
  const float* Wk = (const float*)d_in[2];
  const float* Wv = (const float*)d_in[3];
  const float* Er = (const float*)d_in[4];
  float* out = (float*)d_out;

  cudaFuncSetAttribute(attn_mma, cudaFuncAttributeMaxDynamicSharedMemorySize,
                       SM_FLOATS * 4);

  qkv_mma<<<dim3((BB * TT) / 64), 256>>>(x, Wq, Wk, Wv);
  attn_mma<<<dim3(TT / 64, BB), 256, SM_FLOATS * 4>>>(Er, out);
}

// round 5
// speedup vs baseline: 2.8363x; 1.4661x over previous
#include <cuda_runtime.h>
#include <cstdint>

#define BB 16
#define TT 2048
#define CC 512
#define HH 64
#define SCALE 0.125f

__device__ float g_q[BB * TT * HH];
__device__ float g_k[BB * TT * HH];
__device__ float g_v[BB * TT * HH];

__device__ __forceinline__ uint32_t f2tf(float f) {
  uint32_t u;
  asm("cvt.rna.tf32.f32 %0, %1;" : "=r"(u) : "f"(f));
  return u;
}
__device__ __forceinline__ void split(float x, uint32_t& h, uint32_t& l) {
  h = f2tf(x);
  l = f2tf(x - __uint_as_float(h));
}
__device__ __forceinline__ uint32_t U(float f) { return __float_as_uint(f); }

__device__ __forceinline__ void mma8(float* c, uint32_t a0, uint32_t a1,
                                     uint32_t a2, uint32_t a3, uint32_t b0,
                                     uint32_t b1) {
  asm volatile(
      "mma.sync.aligned.m16n8k8.row.col.f32.tf32.tf32.f32 "
      "{%0,%1,%2,%3}, {%4,%5,%6,%7}, {%8,%9}, {%0,%1,%2,%3};"
      : "+f"(c[0]), "+f"(c[1]), "+f"(c[2]), "+f"(c[3])
      : "r"(a0), "r"(a1), "r"(a2), "r"(a3), "r"(b0), "r"(b1));
}
__device__ __forceinline__ void mma3(float* c, const uint32_t* ah,
                                     const uint32_t* al, uint32_t bh0,
                                     uint32_t bh1, uint32_t bl0, uint32_t bl1) {
  mma8(c, ah[0], ah[1], ah[2], ah[3], bl0, bl1);
  mma8(c, al[0], al[1], al[2], al[3], bh0, bh1);
  mma8(c, ah[0], ah[1], ah[2], ah[3], bh0, bh1);
}

#define SW(row, col) ((col) ^ ((((row) >> 2) & 1) << 2))

// ---------------------------------------------------------------------------
// QKV projection, 3xTF32, W pre-split into hi/lo smem tiles.
// ---------------------------------------------------------------------------
#define PX 40
#define PW 200
#define QKV_SMEM ((64 * PX + 2 * 32 * PW) * 4)
__global__ __launch_bounds__(256) void qkv_mma(const float* __restrict__ x,
                                               const float* __restrict__ Wq,
                                               const float* __restrict__ Wk,
                                               const float* __restrict__ Wv) {
  extern __shared__ float qsm[];
  float* Xs = qsm;             // 64 x PX
  float* Wh = Xs + 64 * PX;    // 32 x PW
  float* Wl = Wh + 32 * PW;    // 32 x PW
  int tid = threadIdx.x, w = tid >> 5, lane = tid & 31;
  int g = lane >> 2, tg = lane & 3;
  int row0 = blockIdx.x * 64;
  int mt = w & 3, nh = w >> 2;
  float acc[12][4] = {};

  for (int k0 = 0; k0 < CC; k0 += 32) {
    __syncthreads();
    for (int i = tid; i < 512; i += 256) {  // X 64x32
      int r = i >> 3, h4 = (i & 7) << 2;
      *(float4*)&Xs[r * PX + SW(r, h4)] =
          *(const float4*)&x[(size_t)(row0 + r) * CC + k0 + h4];
    }
    for (int i = tid; i < 1536; i += 256) {  // W 32x192, pre-split
      int k = i / 48, n4 = (i % 48) * 4;
      int m = n4 >> 6, nn = n4 & 63;
      const float* Wm = m == 0 ? Wq : (m == 1 ? Wk : Wv);
      float4 v4 = *(const float4*)&Wm[(size_t)(k0 + k) * HH + nn];
      uint32_t h0, l0, h1, l1, h2, l2, h3, l3;
      split(v4.x, h0, l0);
      split(v4.y, h1, l1);
      split(v4.z, h2, l2);
      split(v4.w, h3, l3);
      *(float4*)&Wh[k * PW + n4] =
          make_float4(__uint_as_float(h0), __uint_as_float(h1),
                      __uint_as_float(h2), __uint_as_float(h3));
      *(float4*)&Wl[k * PW + n4] =
          make_float4(__uint_as_float(l0), __uint_as_float(l1),
                      __uint_as_float(l2), __uint_as_float(l3));
    }
    __syncthreads();
#pragma unroll
    for (int k8 = 0; k8 < 32; k8 += 8) {
      int r1 = 16 * mt + g, r2 = r1 + 8;
      uint32_t ah[4], al[4];
      split(Xs[r1 * PX + SW(r1, k8 + tg)], ah[0], al[0]);
      split(Xs[r2 * PX + SW(r2, k8 + tg)], ah[1], al[1]);
      split(Xs[r1 * PX + SW(r1, k8 + tg + 4)], ah[2], al[2]);
      split(Xs[r2 * PX + SW(r2, k8 + tg + 4)], ah[3], al[3]);
#pragma unroll
      for (int v = 0; v < 12; v++) {
        int n0 = 8 * (12 * nh + v);
        uint32_t bh0 = U(Wh[(k8 + tg) * PW + n0 + g]);
        uint32_t bl0 = U(Wl[(k8 + tg) * PW + n0 + g]);
        uint32_t bh1 = U(Wh[(k8 + tg + 4) * PW + n0 + g]);
        uint32_t bl1 = U(Wl[(k8 + tg + 4) * PW + n0 + g]);
        mma3(acc[v], ah, al, bh0, bh1, bl0, bl1);
      }
    }
  }
#pragma unroll
  for (int v = 0; v < 12; v++) {
    int ncol = 8 * (12 * nh + v) + 2 * tg;
    int m = ncol >> 6, nn = ncol & 63;
    float* o = m == 0 ? g_q : (m == 1 ? g_k : g_v);
    int r0 = row0 + 16 * mt + g;
    *(float2*)&o[(size_t)r0 * HH + nn] = make_float2(acc[v][0], acc[v][1]);
    *(float2*)&o[(size_t)(r0 + 8) * HH + nn] =
        make_float2(acc[v][2], acc[v][3]);
  }
}

// ---------------------------------------------------------------------------
// Fused attention. Two paired query tiles per CTA (t0, T-64-t0) for balance.
// S,G: 3xTF32. AV: 1xTF32 (P,V pre-rounded to tf32).
// Er band cached circularly: slot(r) = r mod 96, 32 new rows per key tile.
// ---------------------------------------------------------------------------
#define PT 72
#define PS 36
#define PG 104
#define SM_FLOATS \
  (64 * PT + 3 * 32 * PT + 96 * PT + 64 * PS + 32 * PG + 256 + 512)

__global__ __launch_bounds__(256) void attn_mma(const float* __restrict__ Er,
                                                float* __restrict__ out) {
  extern __shared__ float sm[];
  float* Qs = sm;              // 64 x PT
  float* Ks = Qs + 64 * PT;    // 32 x PT
  float* Vs = Ks + 32 * PT;    // 32 x PT (tf32 values)
  float* Qrs = Vs + 32 * PT;   // 32 x PT
  float* Ers = Qrs + 32 * PT;  // 96 x PT circular slots
  float* Ss = Ers + 96 * PT;   // 64 x PS (S, then tf32 P)
  float* Gs = Ss + 64 * PS;    // 32 x PG (cols = slots)
  float* ds = Gs + 32 * PG;    // 64
  float* ms = ds + 64;         // 64
  float* ls = ms + 64;         // 64
  float* as_ = ls + 64;        // 64
  float* pmax = as_ + 64;      // 4 x 64
  float* psum = pmax + 256;    // 4 x 64

  int tid = threadIdx.x, w = tid >> 5, lane = tid & 31;
  int g = lane >> 2, tg = lane & 3;
  int b = blockIdx.y;
  const float* Q = g_q + (size_t)b * TT * HH;
  const float* K = g_k + (size_t)b * TT * HH;
  const float* V = g_v + (size_t)b * TT * HH;

  int smt = w & 3, snh = w >> 2;
  int gmt = w & 1, gnb = w >> 1;
  int sr = tid & 63, sc = (tid >> 6) << 3;

  for (int half = 0; half < 2; half++) {
    int t0 = half == 0 ? blockIdx.x * 64 : (TT - 64 - blockIdx.x * 64);
    __syncthreads();
    for (int i = tid; i < 1024; i += 256) {  // Q tile 64x64
      int r = i >> 4, h4 = (i & 15) << 2;
      *(float4*)&Qs[r * PT + SW(r, h4)] =
          *(const float4*)&Q[(size_t)(t0 + r) * HH + h4];
    }
    __syncthreads();
    if (tid < 64) {
      float acc = 0.f;
      const float* el = Er + (size_t)(TT - 1) * HH;
#pragma unroll
      for (int h = 0; h < HH; h++) acc += Qs[tid * PT + SW(tid, h)] * el[h];
      ds[tid] = acc;
      ms[tid] = -1e30f;
      ls[tid] = 0.f;
    }

    float O[4][4] = {};
    int niter = t0 / 32 + 2;

    for (int it = 0; it < niter; it++) {
      int s0 = it * 32;
      int rbase = t0 - s0 - 33;
      __syncthreads();
      for (int i = tid; i < 512; i += 256) {  // K, V(tf32), Qr tiles 32x64
        int r = i >> 4, h4 = (i & 15) << 2;
        int c = r * PT + SW(r, h4);
        *(float4*)&Ks[c] = *(const float4*)&K[(size_t)(s0 + r) * HH + h4];
        float4 vv = *(const float4*)&V[(size_t)(s0 + r) * HH + h4];
        *(float4*)&Vs[c] = make_float4(
            __uint_as_float(f2tf(vv.x)), __uint_as_float(f2tf(vv.y)),
            __uint_as_float(f2tf(vv.z)), __uint_as_float(f2tf(vv.w)));
        int rq = s0 + 1 + r;
        if (rq > TT - 1) rq = TT - 1;  // clamped rows feed only masked slots
        *(float4*)&Qrs[c] = *(const float4*)&Q[(size_t)rq * HH + h4];
      }
      {  // Er band: 96 slots on first iter, 32 new rows after
        int nel = (it == 0 ? 96 : 32) * 16;
        for (int i = tid; i < nel; i += 256) {
          int xr = i >> 4, h4 = (i & 15) << 2;
          int r = rbase + xr;
          int slot = (r + 2112) % 96;  // 2112 = 22*96 keeps arg positive
          int rc = r < 0 ? 0 : r;      // negative rows unused (masked)
          *(float4*)&Ers[slot * PT + SW(slot, h4)] =
              *(const float4*)&Er[(size_t)rc * HH + h4];
        }
      }
      __syncthreads();

      // S = Q @ K^T (64x32), 3xTF32
      {
        float sf[2][4] = {};
        int r1 = 16 * smt + g, r2 = r1 + 8;
#pragma unroll
        for (int k8 = 0; k8 < 64; k8 += 8) {
          uint32_t ah[4], al[4];
          split(Qs[r1 * PT + SW(r1, k8 + tg)], ah[0], al[0]);
          split(Qs[r2 * PT + SW(r2, k8 + tg)], ah[1], al[1]);
          split(Qs[r1 * PT + SW(r1, k8 + tg + 4)], ah[2], al[2]);
          split(Qs[r2 * PT + SW(r2, k8 + tg + 4)], ah[3], al[3]);
#pragma unroll
          for (int u2 = 0; u2 < 2; u2++) {
            int br = 16 * snh + 8 * u2 + g;
            uint32_t bh0, bl0, bh1, bl1;
            split(Ks[br * PT + SW(br, k8 + tg)], bh0, bl0);
            split(Ks[br * PT + SW(br, k8 + tg + 4)], bh1, bl1);
            mma3(sf[u2], ah, al, bh0, bh1, bl0, bl1);
          }
        }
#pragma unroll
        for (int u2 = 0; u2 < 2; u2++) {
          int n0 = 16 * snh + 8 * u2 + 2 * tg;
          *(float2*)&Ss[r1 * PS + n0] = make_float2(sf[u2][0], sf[u2][1]);
          *(float2*)&Ss[r2 * PS + n0] = make_float2(sf[u2][2], sf[u2][3]);
        }
      }
      // G[j][slot] = Qr[j] . Ers[slot] (32x96), 3xTF32
      {
        float gf[3][4] = {};
        int r1 = 16 * gmt + g, r2 = r1 + 8;
#pragma unroll
        for (int k8 = 0; k8 < 64; k8 += 8) {
          uint32_t ah[4], al[4];
          split(Qrs[r1 * PT + SW(r1, k8 + tg)], ah[0], al[0]);
          split(Qrs[r2 * PT + SW(r2, k8 + tg)], ah[1], al[1]);
          split(Qrs[r1 * PT + SW(r1, k8 + tg + 4)], ah[2], al[2]);
          split(Qrs[r2 * PT + SW(r2, k8 + tg + 4)], ah[3], al[3]);
#pragma unroll
          for (int v = 0; v < 3; v++) {
            int br = 8 * (3 * gnb + v) + g;
            uint32_t bh0, bl0, bh1, bl1;
            split(Ers[br * PT + SW(br, k8 + tg)], bh0, bl0);
            split(Ers[br * PT + SW(br, k8 + tg + 4)], bh1, bl1);
            mma3(gf[v], ah, al, bh0, bh1, bl0, bl1);
          }
        }
#pragma unroll
        for (int v = 0; v < 3; v++) {
          int n0 = 8 * (3 * gnb + v) + 2 * tg;
          *(float2*)&Gs[r1 * PG + n0] = make_float2(gf[v][0], gf[v][1]);
          *(float2*)&Gs[r2 * PG + n0] = make_float2(gf[v][2], gf[v][3]);
        }
      }
      __syncthreads();

      // softmax
      float vvals[8];
      {
        int t = t0 + sr;
        float4 sa = *(const float4*)&Ss[sr * PS + sc];
        float4 sb = *(const float4*)&Ss[sr * PS + sc + 4];
        float sl[8] = {sa.x, sa.y, sa.z, sa.w, sb.x, sb.y, sb.z, sb.w};
        int base = rbase + sr + 31 + 2112;
        float pm = -1e30f;
#pragma unroll
        for (int c = 0; c < 8; c++) {
          int j = sc + c, s = s0 + j;
          float vv = SCALE * sl[c];
          if (s <= t - 2)
            vv += Gs[j * PG + (base - j) % 96];
          else if (s == t)
            vv += ds[sr];
          if (s > t) vv = -1e30f;
          vvals[c] = vv;
          pm = fmaxf(pm, vv);
        }
        pmax[(tid >> 6) * 64 + sr] = pm;
      }
      __syncthreads();
      if (tid < 64) {
        float mo = ms[tid];
        float mn = fmaxf(fmaxf(fmaxf(pmax[tid], pmax[64 + tid]),
                               fmaxf(pmax[128 + tid], pmax[192 + tid])),
                         mo);
        ms[tid] = mn;
        as_[tid] = __expf(mo - mn);
      }
      __syncthreads();
      {
        float mn = ms[sr];
        float p[8];
        float rs = 0.f;
#pragma unroll
        for (int c = 0; c < 8; c++) {
          p[c] = __expf(vvals[c] - mn);
          rs += p[c];
        }
        *(float4*)&Ss[sr * PS + sc] = make_float4(
            __uint_as_float(f2tf(p[0])), __uint_as_float(f2tf(p[1])),
            __uint_as_float(f2tf(p[2])), __uint_as_float(f2tf(p[3])));
        *(float4*)&Ss[sr * PS + sc + 4] = make_float4(
            __uint_as_float(f2tf(p[4])), __uint_as_float(f2tf(p[5])),
            __uint_as_float(f2tf(p[6])), __uint_as_float(f2tf(p[7])));
        psum[(tid >> 6) * 64 + sr] = rs;
        float a1 = as_[16 * smt + g], a2 = as_[16 * smt + g + 8];
#pragma unroll
        for (int v = 0; v < 4; v++) {
          O[v][0] *= a1;
          O[v][1] *= a1;
          O[v][2] *= a2;
          O[v][3] *= a2;
        }
      }
      __syncthreads();
      if (tid < 64)
        ls[tid] = as_[tid] * ls[tid] + (psum[tid] + psum[64 + tid]) +
                  (psum[128 + tid] + psum[192 + tid]);
      // O += P @ V, 1xTF32 (P, V already tf32-rounded)
      {
        int r1 = 16 * smt + g, r2 = r1 + 8;
#pragma unroll
        for (int k8 = 0; k8 < 32; k8 += 8) {
          uint32_t a0 = U(Ss[r1 * PS + k8 + tg]);
          uint32_t a1 = U(Ss[r2 * PS + k8 + tg]);
          uint32_t a2 = U(Ss[r1 * PS + k8 + tg + 4]);
          uint32_t a3 = U(Ss[r2 * PS + k8 + tg + 4]);
#pragma unroll
          for (int v = 0; v < 4; v++) {
            int n0 = 32 * snh + 8 * v;
            int br = k8 + tg;
            uint32_t b0 = U(Vs[br * PT + SW(br, n0 + g)]);
            uint32_t b1 = U(Vs[(br + 4) * PT + SW(br + 4, n0 + g)]);
            mma8(O[v], a0, a1, a2, a3, b0, b1);
          }
        }
      }
    }

    __syncthreads();
    int r1 = 16 * smt + g, r2 = r1 + 8;
    float inv1 = 1.f / ls[r1], inv2 = 1.f / ls[r2];
#pragma unroll
    for (int v = 0; v < 4; v++) {
      int nc = 32 * snh + 8 * v + 2 * tg;
      *(float2*)&out[((size_t)b * TT + t0 + r1) * HH + nc] =
          make_float2(O[v][0] * inv1, O[v][1] * inv1);
      *(float2*)&out[((size_t)b * TT + t0 + r2) * HH + nc] =
          make_float2(O[v][2] * inv2, O[v][3] * inv2);
    }
  }
}

extern "C" void kernel_launch(void* const* d_in, const int* in_sizes, int n_in,
                              void* d_out, int out_size) {
  (void)in_sizes;
  (void)n_in;
  (void)out_size;
  const float* x = (const float*)d_in[0];
  const float* Wq = (const float*)d_in[1];
  const float* Wk = (const float*)d_in[2];
  const float* Wv = (const float*)d_in[3];
  const float* Er = (const float*)d_in[4];
  float* out = (float*)d_out;

  cudaFuncSetAttribute(qkv_mma, cudaFuncAttributeMaxDynamicSharedMemorySize,
                       QKV_SMEM);
  cudaFuncSetAttribute(attn_mma, cudaFuncAttributeMaxDynamicSharedMemorySize,
                       SM_FLOATS * 4);

  qkv_mma<<<dim3((BB * TT) / 64), 256, QKV_SMEM>>>(x, Wq, Wk, Wv);
  attn_mma<<<dim3(TT / 128, BB), 256, SM_FLOATS * 4>>>(Er, out);
}